// round 15
// baseline (speedup 1.0000x reference)
#include <cuda_runtime.h>
#include <cuda_fp16.h>
#include <math.h>
#include <stdint.h>

#define DDIM   512
#define MTOK   32768
#define NCODE  8192
#define MT     128
#define NTILE  128
#define BK     64
#define NSTG   3
#define MARGIN 0.25f
#define CAP    160
#define NTHREADS_TOT 65536          // 256 CTAs x 256 threads
#define SURV_MAX (1 << 20)

#define A_BYTES (MT*BK*2)
#define B_BYTES (NTILE*BK*2)
#define STG_BYTES (A_BYTES + B_BYTES)
#define DYN_SMEM (NSTG * STG_BYTES)   // 96KB

#define SWZ(o) ((o) ^ ((((o) >> 3) & 0x70)))

// ---------------- device scratch ----------------
__device__ __half g_zh[(size_t)MTOK * DDIM];
__device__ __half g_eh[(size_t)NCODE * DDIM];
__device__ float g_enorm[NCODE];
__device__ int   g_counts[NCODE];
__device__ float g_tokloss[MTOK];
__device__ unsigned long long g_key[MTOK];
__device__ unsigned long long g_ent[(size_t)NTHREADS_TOT * CAP];
__device__ int   g_cnt[NTHREADS_TOT];
__device__ unsigned int  g_bestbits[MTOK];
__device__ unsigned char g_overflow[MTOK];
__device__ int   g_surv[SURV_MAX];
__device__ int   g_nsurv;

// ---------------- helpers ----------------
__device__ __forceinline__ uint32_t smem_u32(const void* p) {
    return (uint32_t)__cvta_generic_to_shared(p);
}
__device__ __forceinline__ void cpasync16(uint32_t dst, const void* src) {
    asm volatile("cp.async.cg.shared.global [%0], [%1], 16;" :: "r"(dst), "l"(src) : "memory");
}
__device__ __forceinline__ void cp_commit() {
    asm volatile("cp.async.commit_group;" ::: "memory");
}
template<int N> __device__ __forceinline__ void cp_wait() {
    asm volatile("cp.async.wait_group %0;" :: "n"(N) : "memory");
}
__device__ __forceinline__ void ldsm4(uint32_t& r0, uint32_t& r1, uint32_t& r2, uint32_t& r3,
                                      uint32_t a) {
    asm volatile("ldmatrix.sync.aligned.m8n8.x4.shared.b16 {%0,%1,%2,%3}, [%4];"
                 : "=r"(r0), "=r"(r1), "=r"(r2), "=r"(r3) : "r"(a));
}
__device__ __forceinline__ void mma16816(float* c, const uint32_t* a, const uint32_t* b) {
    asm volatile(
        "mma.sync.aligned.m16n8k16.row.col.f32.f16.f16.f32 "
        "{%0,%1,%2,%3}, {%4,%5,%6,%7}, {%8,%9}, {%0,%1,%2,%3};"
        : "+f"(c[0]), "+f"(c[1]), "+f"(c[2]), "+f"(c[3])
        : "r"(a[0]), "r"(a[1]), "r"(a[2]), "r"(a[3]), "r"(b[0]), "r"(b[1]));
}
__device__ __forceinline__ unsigned orderbits(float v) {
    unsigned u = __float_as_uint(v);
    return (u & 0x80000000u) ? ~u : (u | 0x80000000u);
}
__device__ __forceinline__ float unorderf(unsigned u) {
    u = (u & 0x80000000u) ? (u & 0x7FFFFFFFu) : ~u;
    return __uint_as_float(u);
}
__device__ __forceinline__ unsigned long long packkey(float d, int c) {
    return ((unsigned long long)orderbits(d) << 32) | (unsigned)c;
}

// ---------------- setup ----------------
__global__ void init_kernel() {
    int i = blockIdx.x * blockDim.x + threadIdx.x;
    if (i < NCODE) g_counts[i] = 0;
    if (i < MTOK) {
        g_key[i] = 0xFFFFFFFFFFFFFFFFull;
        g_bestbits[i] = 0xFFFFFFFFu;
        g_overflow[i] = 0;
    }
    if (i == 0) g_nsurv = 0;
}

__global__ void convert_kernel(const float* __restrict__ x, __half* __restrict__ out, int n4) {
    int i = blockIdx.x * blockDim.x + threadIdx.x;
    if (i >= n4) return;
    float4 v = ((const float4*)x)[i];
    ((__half2*)out)[i * 2]     = __floats2half2_rn(v.x, v.y);
    ((__half2*)out)[i * 2 + 1] = __floats2half2_rn(v.z, v.w);
}

__global__ void convert_enorm_kernel(const float* __restrict__ emb, __half* __restrict__ out) {
    int c = blockIdx.x, tid = threadIdx.x;
    const float4* src = (const float4*)(emb + (size_t)c * DDIM);
    float4 v = src[tid];
    ((__half2*)(out + (size_t)c * DDIM))[tid * 2]     = __floats2half2_rn(v.x, v.y);
    ((__half2*)(out + (size_t)c * DDIM))[tid * 2 + 1] = __floats2half2_rn(v.z, v.w);
    float s = v.x * v.x + v.y * v.y + v.z * v.z + v.w * v.w;
    #pragma unroll
    for (int o = 16; o > 0; o >>= 1) s += __shfl_down_sync(0xffffffffu, s, o);
    __shared__ float ws[4];
    if ((tid & 31) == 0) ws[tid >> 5] = s;
    __syncthreads();
    if (tid == 0) g_enorm[c] = ws[0] + ws[1] + ws[2] + ws[3];
}

// ---------------- fused HMMA GEMM + candidate emission + screen-best publish ----------------
__global__ void __launch_bounds__(256, 2) hmma_argmin_kernel(int C) {
    extern __shared__ __align__(1024) char dyn[];
    const uint32_t sb = smem_u32(dyn);
    const int tid = threadIdx.x;
    const int wid = tid >> 5, l = tid & 31;
    const int wm = wid >> 1, wn = wid & 1;
    const int m0 = blockIdx.x * MT;
    const int nct = C / NTILE;
    const int TOT = nct * 8;

    float rbest[4];
    #pragma unroll
    for (int r = 0; r < 4; r++) rbest[r] = 3.0e38f;
    uint32_t mmeta[4];
    #pragma unroll
    for (int r = 0; r < 4; r++) {
        int am = r >> 1, h = r & 1;
        int row = wm * 32 + am * 16 + h * 8 + (l >> 2);
        mmeta[r] = (uint32_t)(m0 + row) << 13;
    }
    int cnt = 0;
    unsigned long long* ent = g_ent + (size_t)(blockIdx.x * 256 + tid) * CAP;

    // ---- hoisted loader state (incremental addressing, no % or recompute) ----
    const int prow = tid >> 3;                 // 0..31
    const int pq   = (tid & 7) * 8;            // half offset within 64
    const uint32_t swz0 = SWZ((uint32_t)(prow * 128 + pq * 2));
    const __half* Abase = g_zh + (size_t)(m0 + prow) * DDIM + pq;
    const __half* Bbase = g_eh + (size_t)prow * DDIM + pq;
    int aoff = 0, boff = 0;                    // in halves
    int lc = 0;
    uint32_t stg_w = 0;

    auto load_next = [&]() {
        uint32_t abase = sb + stg_w + swz0;
        uint32_t bbase = abase + A_BYTES;
        const __half* Ap = Abase + aoff;
        const __half* Bp = Bbase + boff;
        #pragma unroll
        for (int q = 0; q < 4; q++) {
            cpasync16(abase + q * 4096, Ap + (size_t)q * 32 * DDIM);
            cpasync16(bbase + q * 4096, Bp + (size_t)q * 32 * DDIM);
        }
        cp_commit();
        if ((lc & 7) == 7) { aoff = 0; boff += NTILE * DDIM - 448; }
        else { aoff += BK; boff += BK; }
        lc++;
        stg_w += STG_BYTES; if (stg_w == NSTG * STG_BYTES) stg_w = 0;
    };

    load_next();
    load_next();

    float acc[2][8][4];
    #pragma unroll
    for (int am = 0; am < 2; am++)
        #pragma unroll
        for (int bn = 0; bn < 8; bn++)
            #pragma unroll
            for (int k = 0; k < 4; k++) acc[am][bn][k] = 0.f;

    const int arow = wm * 32 + (l & 7) + ((l >> 3) & 1) * 8;
    const int acol = (l >> 4) * 16;
    const uint32_t axor = (uint32_t)((arow & 7) << 4);
    const uint32_t aoff0 = (uint32_t)(arow * 128);
    const int brow = wn * 64 + (l & 7) + (l >> 4) * 8;
    const int bcol = ((l >> 3) & 1) * 16;
    const uint32_t bxor = (uint32_t)((brow & 7) << 4);
    const uint32_t boff0 = (uint32_t)(brow * 128);

    uint32_t stg_r = 0;

    for (int i = 0; i < TOT; i++) {
        if (i + 1 < TOT) cp_wait<1>(); else cp_wait<0>();
        __syncthreads();
        if (lc < TOT) load_next();

        uint32_t abase = sb + stg_r;
        uint32_t bbase = abase + A_BYTES;
        stg_r += STG_BYTES; if (stg_r == NSTG * STG_BYTES) stg_r = 0;

        #pragma unroll
        for (int kk = 0; kk < 4; kk++) {
            const uint32_t akb = ((uint32_t)(kk * 32 + acol)) ^ axor;
            const uint32_t bkb = ((uint32_t)(kk * 32 + bcol)) ^ bxor;
            uint32_t af[2][4];
            #pragma unroll
            for (int am = 0; am < 2; am++)
                ldsm4(af[am][0], af[am][1], af[am][2], af[am][3],
                      abase + aoff0 + (uint32_t)(am * 2048) + akb);
            uint32_t bcur[4], bnxt[4];
            ldsm4(bcur[0], bcur[1], bcur[2], bcur[3], bbase + boff0 + bkb);
            #pragma unroll
            for (int bp = 0; bp < 4; bp++) {
                if (bp < 3)
                    ldsm4(bnxt[0], bnxt[1], bnxt[2], bnxt[3],
                          bbase + boff0 + (uint32_t)((bp + 1) * 2048) + bkb);
                #pragma unroll
                for (int am = 0; am < 2; am++) {
                    mma16816(acc[am][2 * bp],     af[am], bcur);
                    mma16816(acc[am][2 * bp + 1], af[am], bcur + 2);
                }
                #pragma unroll
                for (int q = 0; q < 4; q++) bcur[q] = bnxt[q];
            }
        }

        if ((i & 7) == 7) {
            int c0 = (i >> 3) * NTILE;
            #pragma unroll
            for (int bn = 0; bn < 8; bn++) {
                #pragma unroll
                for (int j = 0; j < 2; j++) {
                    int c = c0 + wn * 64 + bn * 8 + (l & 3) * 2 + j;
                    float e = __ldg(&g_enorm[c]);
                    #pragma unroll
                    for (int am = 0; am < 2; am++) {
                        #pragma unroll
                        for (int h = 0; h < 2; h++) {
                            int r = am * 2 + h;
                            float v = fmaf(-2.f, acc[am][bn][h * 2 + j], e);
                            if (v < rbest[r] + MARGIN) {
                                int pos = cnt < CAP ? cnt : CAP - 1;
                                ent[pos] = ((unsigned long long)(mmeta[r] | (uint32_t)c) << 32)
                                         | __float_as_uint(v);
                                cnt++;
                            }
                            rbest[r] = fminf(rbest[r], v);
                        }
                    }
                }
            }
            #pragma unroll
            for (int am = 0; am < 2; am++)
                #pragma unroll
                for (int bn = 0; bn < 8; bn++)
                    #pragma unroll
                    for (int k = 0; k < 4; k++) acc[am][bn][k] = 0.f;
        }
    }

    g_cnt[blockIdx.x * 256 + tid] = cnt;
    // fused filter A: publish per-slot screen best + inline overflow marking
    #pragma unroll
    for (int r = 0; r < 4; r++) {
        int m = (int)(mmeta[r] >> 13);
        atomicMin(&g_bestbits[m], orderbits(rbest[r]));
        if (cnt > CAP) g_overflow[m] = 1;
    }
}

// ---------------- filter B: compact survivors vs global screen best ----------------
__global__ void filter_b_kernel() {
    int gid = blockIdx.x * blockDim.x + threadIdx.x;
    int cnt = g_cnt[gid];
    if (cnt > CAP) cnt = CAP;
    const unsigned long long* ent = g_ent + (size_t)gid * CAP;
    for (int i = 0; i < cnt; i++) {
        unsigned long long e = ent[i];
        unsigned meta = (unsigned)(e >> 32);
        float v = __uint_as_float((unsigned)e);
        int m = meta >> 13;
        float best = unorderf(g_bestbits[m]);
        if (v < best + MARGIN) {
            int pos = atomicAdd(&g_nsurv, 1);
            if (pos < SURV_MAX) g_surv[pos] = (int)meta;
            else g_overflow[m] = 1;
        }
    }
}

// ---------------- exact fp32 scoring of survivors ----------------
__global__ void __launch_bounds__(256) exact_kernel(const float* __restrict__ z,
                                                    const float* __restrict__ emb) {
    int n = g_nsurv;
    if (n > SURV_MAX) n = SURV_MAX;
    int gw = blockIdx.x * 8 + (threadIdx.x >> 5);
    int l = threadIdx.x & 31;
    const int NW = gridDim.x * 8;
    for (int i = gw; i < n; i += NW) {
        unsigned meta = (unsigned)g_surv[i];
        int m = meta >> 13, c = meta & 0x1FFF;
        const float4* zr = (const float4*)(z + (size_t)m * DDIM);
        const float4* er = (const float4*)(emb + (size_t)c * DDIM);
        float a0 = 0.f, a1 = 0.f;
        #pragma unroll
        for (int q = 0; q < 4; q++) {
            float4 zv = __ldg(zr + q * 32 + l);
            float4 ev = __ldg(er + q * 32 + l);
            a0 = fmaf(zv.x, ev.x, a0);
            a1 = fmaf(zv.y, ev.y, a1);
            a0 = fmaf(zv.z, ev.z, a0);
            a1 = fmaf(zv.w, ev.w, a1);
        }
        float s = a0 + a1;
        #pragma unroll
        for (int o = 16; o > 0; o >>= 1) s += __shfl_down_sync(0xffffffffu, s, o);
        if (l == 0) {
            float v = fmaf(-2.f, s, __ldg(&g_enorm[c]));
            atomicMin(&g_key[m], packkey(v, c));
        }
    }
}

// ---------------- fallback: full exact scan for overflowed tokens (expected none) ----------------
__global__ void __launch_bounds__(256) fallback_kernel(const float* __restrict__ z,
                                                       const float* __restrict__ emb) {
    for (int m = blockIdx.x; m < MTOK; m += gridDim.x) {
        if (!g_overflow[m]) continue;
        int tid = threadIdx.x;
        for (int c = tid; c < NCODE; c += 256) {
            const float* zr = z + (size_t)m * DDIM;
            const float* er = emb + (size_t)c * DDIM;
            float a = 0.f;
            for (int k = 0; k < DDIM; k++) a = fmaf(__ldg(zr + k), __ldg(er + k), a);
            float v = fmaf(-2.f, a, __ldg(&g_enorm[c]));
            atomicMin(&g_key[m], packkey(v, c));
        }
    }
}

// ---------------- gather / stats ----------------
__global__ void gather_kernel(const float* __restrict__ z, const float* __restrict__ emb,
                              float* __restrict__ out, float* __restrict__ outCodes,
                              int writeCodes) {
    int m = blockIdx.x, tid = threadIdx.x;
    int c = (int)(g_key[m] & 0x1FFFull);
    float4 zv = ((const float4*)(z + (size_t)m * DDIM))[tid];
    float4 ev = ((const float4*)(emb + (size_t)c * DDIM))[tid];
    float4 d, s, t;
    d.x = ev.x - zv.x; d.y = ev.y - zv.y; d.z = ev.z - zv.z; d.w = ev.w - zv.w;
    s.x = zv.x + d.x;  s.y = zv.y + d.y;  s.z = zv.z + d.z;  s.w = zv.w + d.w;
    ((float4*)(out + (size_t)m * DDIM))[tid] = s;
    t.x = s.x - zv.x; t.y = s.y - zv.y; t.z = s.z - zv.z; t.w = s.w - zv.w;
    float ls = t.x * t.x + t.y * t.y + t.z * t.z + t.w * t.w;
    #pragma unroll
    for (int o = 16; o > 0; o >>= 1) ls += __shfl_down_sync(0xffffffffu, ls, o);
    __shared__ float ws[4];
    if ((tid & 31) == 0) ws[tid >> 5] = ls;
    __syncthreads();
    if (tid == 0) {
        g_tokloss[m] = ws[0] + ws[1] + ws[2] + ws[3];
        atomicAdd(&g_counts[c], 1);
        if (writeCodes) outCodes[m] = (float)c;
    }
}

__global__ void finalize_kernel(float* __restrict__ outStats, int M, int C, int hasStats) {
    __shared__ float sh[1024];
    int tid = threadIdx.x;
    float s = 0.f;
    for (int i = tid; i < M; i += 1024) s += g_tokloss[i];
    sh[tid] = s; __syncthreads();
    for (int o = 512; o > 0; o >>= 1) { if (tid < o) sh[tid] += sh[tid + o]; __syncthreads(); }
    float loss = 0.25f * sh[0] / ((float)M * (float)DDIM);
    __syncthreads();
    float p = 0.f;
    float invM = 1.f / (float)M;
    for (int i = tid; i < C; i += 1024) {
        float pr = (float)g_counts[i] * invM;
        p += pr * logf(pr + 1e-10f);
    }
    sh[tid] = p; __syncthreads();
    for (int o = 512; o > 0; o >>= 1) { if (tid < o) sh[tid] += sh[tid + o]; __syncthreads(); }
    if (tid == 0 && hasStats) {
        outStats[0] = loss;
        outStats[1] = expf(-sh[0]);
    }
}

extern "C" void kernel_launch(void* const* d_in, const int* in_sizes, int n_in,
                              void* d_out, int out_size) {
    const float* z   = (const float*)d_in[0];
    const float* emb = (const float*)d_in[1];
    float* out = (float*)d_out;

    int M = in_sizes[0] / DDIM;   // 32768
    int C = in_sizes[1] / DDIM;   // 8192

    static int attr_done = 0;
    if (!attr_done) {
        cudaFuncSetAttribute(hmma_argmin_kernel, cudaFuncAttributeMaxDynamicSharedMemorySize, DYN_SMEM);
        attr_done = 1;
    }

    __half* zh; cudaGetSymbolAddress((void**)&zh, g_zh);
    __half* eh; cudaGetSymbolAddress((void**)&eh, g_eh);

    init_kernel<<<(MTOK + 255) / 256, 256>>>();                       // 1
    convert_kernel<<<(M * DDIM / 4 + 255) / 256, 256>>>(z, zh, M * DDIM / 4);  // 2
    convert_enorm_kernel<<<C, 128>>>(emb, eh);                        // 3
    hmma_argmin_kernel<<<M / MT, 256, DYN_SMEM>>>(C);                 // 4  <-- profiled slot
    filter_b_kernel<<<NTHREADS_TOT / 256, 256>>>();                   // 5
    exact_kernel<<<1024, 256>>>(z, emb);                              // 6
    fallback_kernel<<<64, 256>>>(z, emb);                             // 7
    long long zqN = (long long)M * DDIM;
    int writeCodes = (out_size >= zqN + M) ? 1 : 0;
    gather_kernel<<<M, 128>>>(z, emb, out, out + zqN, writeCodes);    // 8
    int hasStats = (out_size >= zqN + M + 2) ? 1 : 0;
    finalize_kernel<<<1, 1024>>>(out + zqN + M, M, C, hasStats);      // 9
}

// round 16
// speedup vs baseline: 1.0953x; 1.0953x over previous
#include <cuda_runtime.h>
#include <cuda_fp16.h>
#include <math.h>
#include <stdint.h>

#define DDIM   512
#define MTOK   32768
#define NCODE  8192
#define MT     128
#define NTILE  128
#define BK     64
#define NSTG   3
#define MARGIN 0.25f
#define CAP    160
#define NTHREADS_TOT 65536          // 256 CTAs x 256 threads
#define SURV_MAX (1 << 20)

#define A_BYTES (MT*BK*2)
#define B_BYTES (NTILE*BK*2)
#define STG_BYTES (A_BYTES + B_BYTES)
#define DYN_SMEM (NSTG * STG_BYTES)   // 96KB

#define SWZ(o) ((o) ^ ((((o) >> 3) & 0x70)))

// ---------------- device scratch ----------------
__device__ __half g_zh[(size_t)MTOK * DDIM];
__device__ __half g_eh[(size_t)NCODE * DDIM];
__device__ float g_enorm[NCODE];
__device__ int   g_counts[NCODE];
__device__ float g_tokloss[MTOK];
__device__ unsigned long long g_key[MTOK];
__device__ unsigned long long g_ent[(size_t)NTHREADS_TOT * CAP];
__device__ int   g_cnt[NTHREADS_TOT];
__device__ unsigned int  g_bestbits[MTOK];
__device__ unsigned char g_overflow[MTOK];
__device__ int   g_surv[SURV_MAX];
__device__ int   g_nsurv;

// ---------------- helpers ----------------
__device__ __forceinline__ uint32_t smem_u32(const void* p) {
    return (uint32_t)__cvta_generic_to_shared(p);
}
__device__ __forceinline__ void cpasync16(uint32_t dst, const void* src) {
    asm volatile("cp.async.cg.shared.global [%0], [%1], 16;" :: "r"(dst), "l"(src) : "memory");
}
__device__ __forceinline__ void cp_commit() {
    asm volatile("cp.async.commit_group;" ::: "memory");
}
template<int N> __device__ __forceinline__ void cp_wait() {
    asm volatile("cp.async.wait_group %0;" :: "n"(N) : "memory");
}
__device__ __forceinline__ void ldsm4(uint32_t& r0, uint32_t& r1, uint32_t& r2, uint32_t& r3,
                                      uint32_t a) {
    asm volatile("ldmatrix.sync.aligned.m8n8.x4.shared.b16 {%0,%1,%2,%3}, [%4];"
                 : "=r"(r0), "=r"(r1), "=r"(r2), "=r"(r3) : "r"(a));
}
__device__ __forceinline__ void mma16816(float* c, const uint32_t* a, const uint32_t* b) {
    asm volatile(
        "mma.sync.aligned.m16n8k16.row.col.f32.f16.f16.f32 "
        "{%0,%1,%2,%3}, {%4,%5,%6,%7}, {%8,%9}, {%0,%1,%2,%3};"
        : "+f"(c[0]), "+f"(c[1]), "+f"(c[2]), "+f"(c[3])
        : "r"(a[0]), "r"(a[1]), "r"(a[2]), "r"(a[3]), "r"(b[0]), "r"(b[1]));
}
__device__ __forceinline__ unsigned orderbits(float v) {
    unsigned u = __float_as_uint(v);
    return (u & 0x80000000u) ? ~u : (u | 0x80000000u);
}
__device__ __forceinline__ float unorderf(unsigned u) {
    u = (u & 0x80000000u) ? (u & 0x7FFFFFFFu) : ~u;
    return __uint_as_float(u);
}
__device__ __forceinline__ unsigned long long packkey(float d, int c) {
    return ((unsigned long long)orderbits(d) << 32) | (unsigned)c;
}

// ---------------- converts (with fused init) ----------------
__global__ void convert_kernel(const float* __restrict__ x, __half* __restrict__ out, int n4) {
    int i = blockIdx.x * blockDim.x + threadIdx.x;
    // fused init of per-token state (first MTOK threads)
    if (i < MTOK) {
        g_key[i] = 0xFFFFFFFFFFFFFFFFull;
        g_bestbits[i] = 0xFFFFFFFFu;
        g_overflow[i] = 0;
    }
    if (i == 0) g_nsurv = 0;
    if (i >= n4) return;
    float4 v = ((const float4*)x)[i];
    ((__half2*)out)[i * 2]     = __floats2half2_rn(v.x, v.y);
    ((__half2*)out)[i * 2 + 1] = __floats2half2_rn(v.z, v.w);
}

__global__ void convert_enorm_kernel(const float* __restrict__ emb, __half* __restrict__ out) {
    int c = blockIdx.x, tid = threadIdx.x;
    if (tid == 0) g_counts[c] = 0;     // fused init
    const float4* src = (const float4*)(emb + (size_t)c * DDIM);
    float4 v = src[tid];
    ((__half2*)(out + (size_t)c * DDIM))[tid * 2]     = __floats2half2_rn(v.x, v.y);
    ((__half2*)(out + (size_t)c * DDIM))[tid * 2 + 1] = __floats2half2_rn(v.z, v.w);
    float s = v.x * v.x + v.y * v.y + v.z * v.z + v.w * v.w;
    #pragma unroll
    for (int o = 16; o > 0; o >>= 1) s += __shfl_down_sync(0xffffffffu, s, o);
    __shared__ float ws[4];
    if ((tid & 31) == 0) ws[tid >> 5] = s;
    __syncthreads();
    if (tid == 0) g_enorm[c] = ws[0] + ws[1] + ws[2] + ws[3];
}

// ---------------- fused HMMA GEMM + candidate emission + screen-best publish ----------------
__global__ void __launch_bounds__(256, 2) hmma_argmin_kernel(int C) {
    extern __shared__ __align__(1024) char dyn[];
    const uint32_t sb = smem_u32(dyn);
    const int tid = threadIdx.x;
    const int wid = tid >> 5, l = tid & 31;
    const int wm = wid >> 1, wn = wid & 1;
    const int m0 = blockIdx.x * MT;
    const int nct = C / NTILE;
    const int TOT = nct * 8;

    float rbest[4];
    #pragma unroll
    for (int r = 0; r < 4; r++) rbest[r] = 3.0e38f;
    uint32_t mmeta[4];
    #pragma unroll
    for (int r = 0; r < 4; r++) {
        int am = r >> 1, h = r & 1;
        int row = wm * 32 + am * 16 + h * 8 + (l >> 2);
        mmeta[r] = (uint32_t)(m0 + row) << 13;
    }
    int cnt = 0;
    unsigned long long* ent = g_ent + (size_t)(blockIdx.x * 256 + tid) * CAP;

    // hoisted incremental loader state
    const int prow = tid >> 3;
    const int pq   = (tid & 7) * 8;
    const uint32_t swz0 = SWZ((uint32_t)(prow * 128 + pq * 2));
    const __half* Abase = g_zh + (size_t)(m0 + prow) * DDIM + pq;
    const __half* Bbase = g_eh + (size_t)prow * DDIM + pq;
    int aoff = 0, boff = 0;
    int lc = 0;
    uint32_t stg_w = 0;

    auto load_next = [&]() {
        uint32_t abase = sb + stg_w + swz0;
        uint32_t bbase = abase + A_BYTES;
        const __half* Ap = Abase + aoff;
        const __half* Bp = Bbase + boff;
        #pragma unroll
        for (int q = 0; q < 4; q++) {
            cpasync16(abase + q * 4096, Ap + (size_t)q * 32 * DDIM);
            cpasync16(bbase + q * 4096, Bp + (size_t)q * 32 * DDIM);
        }
        cp_commit();
        if ((lc & 7) == 7) { aoff = 0; boff += NTILE * DDIM - 448; }
        else { aoff += BK; boff += BK; }
        lc++;
        stg_w += STG_BYTES; if (stg_w == NSTG * STG_BYTES) stg_w = 0;
    };

    load_next();
    load_next();

    float acc[2][8][4];
    #pragma unroll
    for (int am = 0; am < 2; am++)
        #pragma unroll
        for (int bn = 0; bn < 8; bn++)
            #pragma unroll
            for (int k = 0; k < 4; k++) acc[am][bn][k] = 0.f;

    const int arow = wm * 32 + (l & 7) + ((l >> 3) & 1) * 8;
    const int acol = (l >> 4) * 16;
    const uint32_t axor = (uint32_t)((arow & 7) << 4);
    const uint32_t aoff0 = (uint32_t)(arow * 128);
    const int brow = wn * 64 + (l & 7) + (l >> 4) * 8;
    const int bcol = ((l >> 3) & 1) * 16;
    const uint32_t bxor = (uint32_t)((brow & 7) << 4);
    const uint32_t boff0 = (uint32_t)(brow * 128);

    uint32_t stg_r = 0;

    for (int i = 0; i < TOT; i++) {
        if (i + 1 < TOT) cp_wait<1>(); else cp_wait<0>();
        __syncthreads();
        if (lc < TOT) load_next();

        uint32_t abase = sb + stg_r;
        uint32_t bbase = abase + A_BYTES;
        stg_r += STG_BYTES; if (stg_r == NSTG * STG_BYTES) stg_r = 0;

        #pragma unroll
        for (int kk = 0; kk < 4; kk++) {
            const uint32_t akb = ((uint32_t)(kk * 32 + acol)) ^ axor;
            const uint32_t bkb = ((uint32_t)(kk * 32 + bcol)) ^ bxor;
            uint32_t af[2][4];
            #pragma unroll
            for (int am = 0; am < 2; am++)
                ldsm4(af[am][0], af[am][1], af[am][2], af[am][3],
                      abase + aoff0 + (uint32_t)(am * 2048) + akb);
            uint32_t bcur[4], bnxt[4];
            ldsm4(bcur[0], bcur[1], bcur[2], bcur[3], bbase + boff0 + bkb);
            #pragma unroll
            for (int bp = 0; bp < 4; bp++) {
                if (bp < 3)
                    ldsm4(bnxt[0], bnxt[1], bnxt[2], bnxt[3],
                          bbase + boff0 + (uint32_t)((bp + 1) * 2048) + bkb);
                #pragma unroll
                for (int am = 0; am < 2; am++) {
                    mma16816(acc[am][2 * bp],     af[am], bcur);
                    mma16816(acc[am][2 * bp + 1], af[am], bcur + 2);
                }
                #pragma unroll
                for (int q = 0; q < 4; q++) bcur[q] = bnxt[q];
            }
        }

        if ((i & 7) == 7) {
            int c0 = (i >> 3) * NTILE;
            #pragma unroll
            for (int bn = 0; bn < 8; bn++) {
                #pragma unroll
                for (int j = 0; j < 2; j++) {
                    int c = c0 + wn * 64 + bn * 8 + (l & 3) * 2 + j;
                    float e = __ldg(&g_enorm[c]);
                    #pragma unroll
                    for (int am = 0; am < 2; am++) {
                        #pragma unroll
                        for (int h = 0; h < 2; h++) {
                            int r = am * 2 + h;
                            float v = fmaf(-2.f, acc[am][bn][h * 2 + j], e);
                            if (v < rbest[r] + MARGIN) {
                                int pos = cnt < CAP ? cnt : CAP - 1;
                                ent[pos] = ((unsigned long long)(mmeta[r] | (uint32_t)c) << 32)
                                         | __float_as_uint(v);
                                cnt++;
                            }
                            rbest[r] = fminf(rbest[r], v);
                        }
                    }
                }
            }
            #pragma unroll
            for (int am = 0; am < 2; am++)
                #pragma unroll
                for (int bn = 0; bn < 8; bn++)
                    #pragma unroll
                    for (int k = 0; k < 4; k++) acc[am][bn][k] = 0.f;
        }
    }

    g_cnt[blockIdx.x * 256 + tid] = cnt;
    #pragma unroll
    for (int r = 0; r < 4; r++) {
        int m = (int)(mmeta[r] >> 13);
        atomicMin(&g_bestbits[m], orderbits(rbest[r]));
        if (cnt > CAP) g_overflow[m] = 1;
    }
}

// ---------------- filter B: compact survivors vs global screen best ----------------
__global__ void filter_b_kernel() {
    int gid = blockIdx.x * blockDim.x + threadIdx.x;
    int cnt = g_cnt[gid];
    if (cnt > CAP) cnt = CAP;
    const unsigned long long* ent = g_ent + (size_t)gid * CAP;
    int i = 0;
    for (; i + 2 <= cnt; i += 2) {
        unsigned long long e0 = ent[i], e1 = ent[i + 1];
        unsigned meta0 = (unsigned)(e0 >> 32), meta1 = (unsigned)(e1 >> 32);
        float v0 = __uint_as_float((unsigned)e0);
        float v1 = __uint_as_float((unsigned)e1);
        int m0 = meta0 >> 13, m1 = meta1 >> 13;
        float b0 = unorderf(g_bestbits[m0]);
        float b1 = unorderf(g_bestbits[m1]);
        if (v0 < b0 + MARGIN) {
            int pos = atomicAdd(&g_nsurv, 1);
            if (pos < SURV_MAX) g_surv[pos] = (int)meta0; else g_overflow[m0] = 1;
        }
        if (v1 < b1 + MARGIN) {
            int pos = atomicAdd(&g_nsurv, 1);
            if (pos < SURV_MAX) g_surv[pos] = (int)meta1; else g_overflow[m1] = 1;
        }
    }
    for (; i < cnt; i++) {
        unsigned long long e = ent[i];
        unsigned meta = (unsigned)(e >> 32);
        float v = __uint_as_float((unsigned)e);
        int m = meta >> 13;
        float best = unorderf(g_bestbits[m]);
        if (v < best + MARGIN) {
            int pos = atomicAdd(&g_nsurv, 1);
            if (pos < SURV_MAX) g_surv[pos] = (int)meta; else g_overflow[m] = 1;
        }
    }
}

// ---------------- exact fp32 scoring of survivors ----------------
__global__ void __launch_bounds__(256) exact_kernel(const float* __restrict__ z,
                                                    const float* __restrict__ emb) {
    int n = g_nsurv;
    if (n > SURV_MAX) n = SURV_MAX;
    int gw = blockIdx.x * 8 + (threadIdx.x >> 5);
    int l = threadIdx.x & 31;
    const int NW = gridDim.x * 8;
    for (int i = gw; i < n; i += NW) {
        unsigned meta = (unsigned)g_surv[i];
        int m = meta >> 13, c = meta & 0x1FFF;
        const float4* zr = (const float4*)(z + (size_t)m * DDIM);
        const float4* er = (const float4*)(emb + (size_t)c * DDIM);
        float a0 = 0.f, a1 = 0.f;
        #pragma unroll
        for (int q = 0; q < 4; q++) {
            float4 zv = __ldg(zr + q * 32 + l);
            float4 ev = __ldg(er + q * 32 + l);
            a0 = fmaf(zv.x, ev.x, a0);
            a1 = fmaf(zv.y, ev.y, a1);
            a0 = fmaf(zv.z, ev.z, a0);
            a1 = fmaf(zv.w, ev.w, a1);
        }
        float s = a0 + a1;
        #pragma unroll
        for (int o = 16; o > 0; o >>= 1) s += __shfl_down_sync(0xffffffffu, s, o);
        if (l == 0) {
            float v = fmaf(-2.f, s, __ldg(&g_enorm[c]));
            atomicMin(&g_key[m], packkey(v, c));
        }
    }
}

// ---------------- fallback: full exact scan for overflowed tokens (expected none) ----------------
__global__ void __launch_bounds__(256) fallback_kernel(const float* __restrict__ z,
                                                       const float* __restrict__ emb) {
    for (int m = blockIdx.x; m < MTOK; m += gridDim.x) {
        if (!g_overflow[m]) continue;
        int tid = threadIdx.x;
        for (int c = tid; c < NCODE; c += 256) {
            const float* zr = z + (size_t)m * DDIM;
            const float* er = emb + (size_t)c * DDIM;
            float a = 0.f;
            for (int k = 0; k < DDIM; k++) a = fmaf(__ldg(zr + k), __ldg(er + k), a);
            float v = fmaf(-2.f, a, __ldg(&g_enorm[c]));
            atomicMin(&g_key[m], packkey(v, c));
        }
    }
}

// ---------------- gather / stats ----------------
__global__ void gather_kernel(const float* __restrict__ z, const float* __restrict__ emb,
                              float* __restrict__ out, float* __restrict__ outCodes,
                              int writeCodes) {
    int m = blockIdx.x, tid = threadIdx.x;
    int c = (int)(g_key[m] & 0x1FFFull);
    float4 zv = ((const float4*)(z + (size_t)m * DDIM))[tid];
    float4 ev = ((const float4*)(emb + (size_t)c * DDIM))[tid];
    float4 d, s, t;
    d.x = ev.x - zv.x; d.y = ev.y - zv.y; d.z = ev.z - zv.z; d.w = ev.w - zv.w;
    s.x = zv.x + d.x;  s.y = zv.y + d.y;  s.z = zv.z + d.z;  s.w = zv.w + d.w;
    ((float4*)(out + (size_t)m * DDIM))[tid] = s;
    t.x = s.x - zv.x; t.y = s.y - zv.y; t.z = s.z - zv.z; t.w = s.w - zv.w;
    float ls = t.x * t.x + t.y * t.y + t.z * t.z + t.w * t.w;
    #pragma unroll
    for (int o = 16; o > 0; o >>= 1) ls += __shfl_down_sync(0xffffffffu, ls, o);
    __shared__ float ws[4];
    if ((tid & 31) == 0) ws[tid >> 5] = ls;
    __syncthreads();
    if (tid == 0) {
        g_tokloss[m] = ws[0] + ws[1] + ws[2] + ws[3];
        atomicAdd(&g_counts[c], 1);
        if (writeCodes) outCodes[m] = (float)c;
    }
}

__global__ void finalize_kernel(float* __restrict__ outStats, int M, int C, int hasStats) {
    __shared__ float sh[1024];
    int tid = threadIdx.x;
    float s = 0.f;
    for (int i = tid; i < M; i += 1024) s += g_tokloss[i];
    sh[tid] = s; __syncthreads();
    for (int o = 512; o > 0; o >>= 1) { if (tid < o) sh[tid] += sh[tid + o]; __syncthreads(); }
    float loss = 0.25f * sh[0] / ((float)M * (float)DDIM);
    __syncthreads();
    float p = 0.f;
    float invM = 1.f / (float)M;
    for (int i = tid; i < C; i += 1024) {
        float pr = (float)g_counts[i] * invM;
        p += pr * logf(pr + 1e-10f);
    }
    sh[tid] = p; __syncthreads();
    for (int o = 512; o > 0; o >>= 1) { if (tid < o) sh[tid] += sh[tid + o]; __syncthreads(); }
    if (tid == 0 && hasStats) {
        outStats[0] = loss;
        outStats[1] = expf(-sh[0]);
    }
}

extern "C" void kernel_launch(void* const* d_in, const int* in_sizes, int n_in,
                              void* d_out, int out_size) {
    const float* z   = (const float*)d_in[0];
    const float* emb = (const float*)d_in[1];
    float* out = (float*)d_out;

    int M = in_sizes[0] / DDIM;   // 32768
    int C = in_sizes[1] / DDIM;   // 8192

    static int attr_done = 0;
    if (!attr_done) {
        cudaFuncSetAttribute(hmma_argmin_kernel, cudaFuncAttributeMaxDynamicSharedMemorySize, DYN_SMEM);
        attr_done = 1;
    }

    __half* zh; cudaGetSymbolAddress((void**)&zh, g_zh);
    __half* eh; cudaGetSymbolAddress((void**)&eh, g_eh);

    convert_kernel<<<(M * DDIM / 4 + 255) / 256, 256>>>(z, zh, M * DDIM / 4); // 1 (init fused)
    convert_enorm_kernel<<<C, 128>>>(emb, eh);                        // 2 (counts init fused)
    hmma_argmin_kernel<<<M / MT, 256, DYN_SMEM>>>(C);                 // 3
    filter_b_kernel<<<NTHREADS_TOT / 256, 256>>>();                   // 4
    exact_kernel<<<1024, 256>>>(z, emb);                              // 5
    fallback_kernel<<<256, 256>>>(z, emb);                            // 6
    long long zqN = (long long)M * DDIM;
    int writeCodes = (out_size >= zqN + M) ? 1 : 0;
    gather_kernel<<<M, 128>>>(z, emb, out, out + zqN, writeCodes);    // 7
    int hasStats = (out_size >= zqN + M + 2) ? 1 : 0;
    finalize_kernel<<<1, 1024>>>(out + zqN + M, M, C, hasStats);      // 8
}

// round 17
// speedup vs baseline: 1.1431x; 1.0436x over previous
#include <cuda_runtime.h>
#include <cuda_fp16.h>
#include <math.h>
#include <stdint.h>

#define DDIM   512
#define MTOK   32768
#define NCODE  8192
#define MT     128
#define NTILE  128
#define BK     64
#define NSTG   3
#define MARGIN 0.25f
#define CAP    160
#define NTHREADS_TOT 65536          // 256 CTAs x 256 threads
#define SURV_MAX (1 << 20)

#define A_BYTES (MT*BK*2)
#define B_BYTES (NTILE*BK*2)
#define STG_BYTES (A_BYTES + B_BYTES)
#define DYN_SMEM (NSTG * STG_BYTES)   // 96KB

#define SWZ(o) ((o) ^ ((((o) >> 3) & 0x70)))

// ---------------- device scratch ----------------
__device__ __half g_zh[(size_t)MTOK * DDIM];
__device__ __half g_eh[(size_t)NCODE * DDIM];
__device__ float g_enorm[NCODE];
__device__ int   g_counts[NCODE];
__device__ float g_tokloss[MTOK];
__device__ unsigned long long g_key[MTOK];
__device__ unsigned long long g_ent[(size_t)NTHREADS_TOT * CAP];
__device__ int   g_cnt[NTHREADS_TOT];
__device__ unsigned int  g_bestbits[MTOK];
__device__ unsigned char g_overflow[MTOK];
__device__ int   g_surv[SURV_MAX];
__device__ int   g_nsurv;

// ---------------- helpers ----------------
__device__ __forceinline__ uint32_t smem_u32(const void* p) {
    return (uint32_t)__cvta_generic_to_shared(p);
}
__device__ __forceinline__ void cpasync16(uint32_t dst, const void* src) {
    asm volatile("cp.async.cg.shared.global [%0], [%1], 16;" :: "r"(dst), "l"(src) : "memory");
}
__device__ __forceinline__ void cp_commit() {
    asm volatile("cp.async.commit_group;" ::: "memory");
}
template<int N> __device__ __forceinline__ void cp_wait() {
    asm volatile("cp.async.wait_group %0;" :: "n"(N) : "memory");
}
__device__ __forceinline__ void ldsm4(uint32_t& r0, uint32_t& r1, uint32_t& r2, uint32_t& r3,
                                      uint32_t a) {
    asm volatile("ldmatrix.sync.aligned.m8n8.x4.shared.b16 {%0,%1,%2,%3}, [%4];"
                 : "=r"(r0), "=r"(r1), "=r"(r2), "=r"(r3) : "r"(a));
}
__device__ __forceinline__ void mma16816(float* c, const uint32_t* a, const uint32_t* b) {
    asm volatile(
        "mma.sync.aligned.m16n8k16.row.col.f32.f16.f16.f32 "
        "{%0,%1,%2,%3}, {%4,%5,%6,%7}, {%8,%9}, {%0,%1,%2,%3};"
        : "+f"(c[0]), "+f"(c[1]), "+f"(c[2]), "+f"(c[3])
        : "r"(a[0]), "r"(a[1]), "r"(a[2]), "r"(a[3]), "r"(b[0]), "r"(b[1]));
}
__device__ __forceinline__ unsigned orderbits(float v) {
    unsigned u = __float_as_uint(v);
    return (u & 0x80000000u) ? ~u : (u | 0x80000000u);
}
__device__ __forceinline__ float unorderf(unsigned u) {
    u = (u & 0x80000000u) ? (u & 0x7FFFFFFFu) : ~u;
    return __uint_as_float(u);
}
__device__ __forceinline__ unsigned long long packkey(float d, int c) {
    return ((unsigned long long)orderbits(d) << 32) | (unsigned)c;
}

// ---------------- converts (with fused init) ----------------
__global__ void convert_kernel(const float* __restrict__ x, __half* __restrict__ out, int n4) {
    int i = blockIdx.x * blockDim.x + threadIdx.x;
    if (i < MTOK) {
        g_key[i] = 0xFFFFFFFFFFFFFFFFull;
        g_bestbits[i] = 0xFFFFFFFFu;
        g_overflow[i] = 0;
    }
    if (i == 0) g_nsurv = 0;
    if (i >= n4) return;
    float4 v = ((const float4*)x)[i];
    ((__half2*)out)[i * 2]     = __floats2half2_rn(v.x, v.y);
    ((__half2*)out)[i * 2 + 1] = __floats2half2_rn(v.z, v.w);
}

__global__ void convert_enorm_kernel(const float* __restrict__ emb, __half* __restrict__ out) {
    int c = blockIdx.x, tid = threadIdx.x;
    if (tid == 0) g_counts[c] = 0;
    const float4* src = (const float4*)(emb + (size_t)c * DDIM);
    float4 v = src[tid];
    ((__half2*)(out + (size_t)c * DDIM))[tid * 2]     = __floats2half2_rn(v.x, v.y);
    ((__half2*)(out + (size_t)c * DDIM))[tid * 2 + 1] = __floats2half2_rn(v.z, v.w);
    float s = v.x * v.x + v.y * v.y + v.z * v.z + v.w * v.w;
    #pragma unroll
    for (int o = 16; o > 0; o >>= 1) s += __shfl_down_sync(0xffffffffu, s, o);
    __shared__ float ws[4];
    if ((tid & 31) == 0) ws[tid >> 5] = s;
    __syncthreads();
    if (tid == 0) g_enorm[c] = ws[0] + ws[1] + ws[2] + ws[3];
}

// ---------------- fused HMMA GEMM + candidate emission + screen-best publish ----------------
__global__ void __launch_bounds__(256, 2) hmma_argmin_kernel(int C) {
    extern __shared__ __align__(1024) char dyn[];
    const uint32_t sb = smem_u32(dyn);
    const int tid = threadIdx.x;
    const int wid = tid >> 5, l = tid & 31;
    const int wm = wid >> 1, wn = wid & 1;
    const int m0 = blockIdx.x * MT;
    const int nct = C / NTILE;
    const int TOT = nct * 8;

    float rbest[4];
    #pragma unroll
    for (int r = 0; r < 4; r++) rbest[r] = 3.0e38f;
    uint32_t mmeta[4];
    #pragma unroll
    for (int r = 0; r < 4; r++) {
        int am = r >> 1, h = r & 1;
        int row = wm * 32 + am * 16 + h * 8 + (l >> 2);
        mmeta[r] = (uint32_t)(m0 + row) << 13;
    }
    int cnt = 0;
    unsigned long long* ent = g_ent + (size_t)(blockIdx.x * 256 + tid) * CAP;

    const int prow = tid >> 3;
    const int pq   = (tid & 7) * 8;
    const uint32_t swz0 = SWZ((uint32_t)(prow * 128 + pq * 2));
    const __half* Abase = g_zh + (size_t)(m0 + prow) * DDIM + pq;
    const __half* Bbase = g_eh + (size_t)prow * DDIM + pq;
    int aoff = 0, boff = 0;
    int lc = 0;
    uint32_t stg_w = 0;

    auto load_next = [&]() {
        uint32_t abase = sb + stg_w + swz0;
        uint32_t bbase = abase + A_BYTES;
        const __half* Ap = Abase + aoff;
        const __half* Bp = Bbase + boff;
        #pragma unroll
        for (int q = 0; q < 4; q++) {
            cpasync16(abase + q * 4096, Ap + (size_t)q * 32 * DDIM);
            cpasync16(bbase + q * 4096, Bp + (size_t)q * 32 * DDIM);
        }
        cp_commit();
        if ((lc & 7) == 7) { aoff = 0; boff += NTILE * DDIM - 448; }
        else { aoff += BK; boff += BK; }
        lc++;
        stg_w += STG_BYTES; if (stg_w == NSTG * STG_BYTES) stg_w = 0;
    };

    load_next();
    load_next();

    float acc[2][8][4];
    #pragma unroll
    for (int am = 0; am < 2; am++)
        #pragma unroll
        for (int bn = 0; bn < 8; bn++)
            #pragma unroll
            for (int k = 0; k < 4; k++) acc[am][bn][k] = 0.f;

    const int arow = wm * 32 + (l & 7) + ((l >> 3) & 1) * 8;
    const int acol = (l >> 4) * 16;
    const uint32_t axor = (uint32_t)((arow & 7) << 4);
    const uint32_t aoff0 = (uint32_t)(arow * 128);
    const int brow = wn * 64 + (l & 7) + (l >> 4) * 8;
    const int bcol = ((l >> 3) & 1) * 16;
    const uint32_t bxor = (uint32_t)((brow & 7) << 4);
    const uint32_t boff0 = (uint32_t)(brow * 128);

    uint32_t stg_r = 0;

    for (int i = 0; i < TOT; i++) {
        if (i + 1 < TOT) cp_wait<1>(); else cp_wait<0>();
        __syncthreads();
        if (lc < TOT) load_next();

        uint32_t abase = sb + stg_r;
        uint32_t bbase = abase + A_BYTES;
        stg_r += STG_BYTES; if (stg_r == NSTG * STG_BYTES) stg_r = 0;

        #pragma unroll
        for (int kk = 0; kk < 4; kk++) {
            const uint32_t akb = ((uint32_t)(kk * 32 + acol)) ^ axor;
            const uint32_t bkb = ((uint32_t)(kk * 32 + bcol)) ^ bxor;
            uint32_t af[2][4];
            #pragma unroll
            for (int am = 0; am < 2; am++)
                ldsm4(af[am][0], af[am][1], af[am][2], af[am][3],
                      abase + aoff0 + (uint32_t)(am * 2048) + akb);
            uint32_t bcur[4], bnxt[4];
            ldsm4(bcur[0], bcur[1], bcur[2], bcur[3], bbase + boff0 + bkb);
            #pragma unroll
            for (int bp = 0; bp < 4; bp++) {
                if (bp < 3)
                    ldsm4(bnxt[0], bnxt[1], bnxt[2], bnxt[3],
                          bbase + boff0 + (uint32_t)((bp + 1) * 2048) + bkb);
                #pragma unroll
                for (int am = 0; am < 2; am++) {
                    mma16816(acc[am][2 * bp],     af[am], bcur);
                    mma16816(acc[am][2 * bp + 1], af[am], bcur + 2);
                }
                #pragma unroll
                for (int q = 0; q < 4; q++) bcur[q] = bnxt[q];
            }
        }

        if ((i & 7) == 7) {
            int c0 = (i >> 3) * NTILE;
            #pragma unroll
            for (int bn = 0; bn < 8; bn++) {
                #pragma unroll
                for (int j = 0; j < 2; j++) {
                    int c = c0 + wn * 64 + bn * 8 + (l & 3) * 2 + j;
                    float e = __ldg(&g_enorm[c]);
                    #pragma unroll
                    for (int am = 0; am < 2; am++) {
                        #pragma unroll
                        for (int h = 0; h < 2; h++) {
                            int r = am * 2 + h;
                            float v = fmaf(-2.f, acc[am][bn][h * 2 + j], e);
                            if (v < rbest[r] + MARGIN) {
                                int pos = cnt < CAP ? cnt : CAP - 1;
                                ent[pos] = ((unsigned long long)(mmeta[r] | (uint32_t)c) << 32)
                                         | __float_as_uint(v);
                                cnt++;
                            }
                            rbest[r] = fminf(rbest[r], v);
                        }
                    }
                }
            }
            #pragma unroll
            for (int am = 0; am < 2; am++)
                #pragma unroll
                for (int bn = 0; bn < 8; bn++)
                    #pragma unroll
                    for (int k = 0; k < 4; k++) acc[am][bn][k] = 0.f;
        }
    }

    g_cnt[blockIdx.x * 256 + tid] = cnt;
    #pragma unroll
    for (int r = 0; r < 4; r++) {
        int m = (int)(mmeta[r] >> 13);
        atomicMin(&g_bestbits[m], orderbits(rbest[r]));
        if (cnt > CAP) g_overflow[m] = 1;
    }
}

// ---------------- filter B: compact survivors vs global screen best ----------------
__global__ void filter_b_kernel() {
    int gid = blockIdx.x * blockDim.x + threadIdx.x;
    int cnt = g_cnt[gid];
    if (cnt > CAP) cnt = CAP;
    const unsigned long long* ent = g_ent + (size_t)gid * CAP;
    int i = 0;
    for (; i + 2 <= cnt; i += 2) {
        unsigned long long e0 = ent[i], e1 = ent[i + 1];
        unsigned meta0 = (unsigned)(e0 >> 32), meta1 = (unsigned)(e1 >> 32);
        float v0 = __uint_as_float((unsigned)e0);
        float v1 = __uint_as_float((unsigned)e1);
        int m0 = meta0 >> 13, m1 = meta1 >> 13;
        float b0 = unorderf(g_bestbits[m0]);
        float b1 = unorderf(g_bestbits[m1]);
        if (v0 < b0 + MARGIN) {
            int pos = atomicAdd(&g_nsurv, 1);
            if (pos < SURV_MAX) g_surv[pos] = (int)meta0; else g_overflow[m0] = 1;
        }
        if (v1 < b1 + MARGIN) {
            int pos = atomicAdd(&g_nsurv, 1);
            if (pos < SURV_MAX) g_surv[pos] = (int)meta1; else g_overflow[m1] = 1;
        }
    }
    for (; i < cnt; i++) {
        unsigned long long e = ent[i];
        unsigned meta = (unsigned)(e >> 32);
        float v = __uint_as_float((unsigned)e);
        int m = meta >> 13;
        float best = unorderf(g_bestbits[m]);
        if (v < best + MARGIN) {
            int pos = atomicAdd(&g_nsurv, 1);
            if (pos < SURV_MAX) g_surv[pos] = (int)meta; else g_overflow[m] = 1;
        }
    }
}

// ---------------- exact fp32 scoring of survivors + fused overflow fallback ----------------
__global__ void __launch_bounds__(256) exact_kernel(const float* __restrict__ z,
                                                    const float* __restrict__ emb) {
    int n = g_nsurv;
    if (n > SURV_MAX) n = SURV_MAX;
    int gw = blockIdx.x * 8 + (threadIdx.x >> 5);
    int l = threadIdx.x & 31;
    const int NW = gridDim.x * 8;
    for (int i = gw; i < n; i += NW) {
        unsigned meta = (unsigned)g_surv[i];
        int m = meta >> 13, c = meta & 0x1FFF;
        const float4* zr = (const float4*)(z + (size_t)m * DDIM);
        const float4* er = (const float4*)(emb + (size_t)c * DDIM);
        float a0 = 0.f, a1 = 0.f;
        #pragma unroll
        for (int q = 0; q < 4; q++) {
            float4 zv = __ldg(zr + q * 32 + l);
            float4 ev = __ldg(er + q * 32 + l);
            a0 = fmaf(zv.x, ev.x, a0);
            a1 = fmaf(zv.y, ev.y, a1);
            a0 = fmaf(zv.z, ev.z, a0);
            a1 = fmaf(zv.w, ev.w, a1);
        }
        float s = a0 + a1;
        #pragma unroll
        for (int o = 16; o > 0; o >>= 1) s += __shfl_down_sync(0xffffffffu, s, o);
        if (l == 0) {
            float v = fmaf(-2.f, s, __ldg(&g_enorm[c]));
            atomicMin(&g_key[m], packkey(v, c));
        }
    }

    // fused fallback: full exact scan for overflowed tokens (expected none)
    for (int m = blockIdx.x; m < MTOK; m += gridDim.x) {
        if (!g_overflow[m]) continue;
        int tid = threadIdx.x;
        for (int c = tid; c < NCODE; c += 256) {
            const float* zr = z + (size_t)m * DDIM;
            const float* er = emb + (size_t)c * DDIM;
            float a = 0.f;
            for (int k = 0; k < DDIM; k++) a = fmaf(__ldg(zr + k), __ldg(er + k), a);
            float v = fmaf(-2.f, a, __ldg(&g_enorm[c]));
            atomicMin(&g_key[m], packkey(v, c));
        }
    }
}

// ---------------- gather / stats: 2 tokens per 256-thread block ----------------
__global__ void __launch_bounds__(256) gather_kernel(const float* __restrict__ z,
                                                     const float* __restrict__ emb,
                                                     float* __restrict__ out,
                                                     float* __restrict__ outCodes,
                                                     int writeCodes) {
    int half = threadIdx.x >> 7;              // 0 or 1: which token
    int tid  = threadIdx.x & 127;
    int m = blockIdx.x * 2 + half;
    int c = (int)(g_key[m] & 0x1FFFull);
    float4 zv = ((const float4*)(z + (size_t)m * DDIM))[tid];
    float4 ev = ((const float4*)(emb + (size_t)c * DDIM))[tid];
    float4 d, s, t;
    d.x = ev.x - zv.x; d.y = ev.y - zv.y; d.z = ev.z - zv.z; d.w = ev.w - zv.w;
    s.x = zv.x + d.x;  s.y = zv.y + d.y;  s.z = zv.z + d.z;  s.w = zv.w + d.w;
    ((float4*)(out + (size_t)m * DDIM))[tid] = s;
    t.x = s.x - zv.x; t.y = s.y - zv.y; t.z = s.z - zv.z; t.w = s.w - zv.w;
    float ls = t.x * t.x + t.y * t.y + t.z * t.z + t.w * t.w;
    #pragma unroll
    for (int o = 16; o > 0; o >>= 1) ls += __shfl_down_sync(0xffffffffu, ls, o);
    __shared__ float ws[2][4];
    if ((tid & 31) == 0) ws[half][tid >> 5] = ls;
    __syncthreads();
    if (tid == 0) {
        g_tokloss[m] = ws[half][0] + ws[half][1] + ws[half][2] + ws[half][3];
        atomicAdd(&g_counts[c], 1);
        if (writeCodes) outCodes[m] = (float)c;
    }
}

__global__ void finalize_kernel(float* __restrict__ outStats, int M, int C, int hasStats) {
    __shared__ float sh[1024];
    int tid = threadIdx.x;
    float s = 0.f;
    for (int i = tid; i < M; i += 1024) s += g_tokloss[i];
    sh[tid] = s; __syncthreads();
    for (int o = 512; o > 0; o >>= 1) { if (tid < o) sh[tid] += sh[tid + o]; __syncthreads(); }
    float loss = 0.25f * sh[0] / ((float)M * (float)DDIM);
    __syncthreads();
    float p = 0.f;
    float invM = 1.f / (float)M;
    for (int i = tid; i < C; i += 1024) {
        float pr = (float)g_counts[i] * invM;
        p += pr * logf(pr + 1e-10f);
    }
    sh[tid] = p; __syncthreads();
    for (int o = 512; o > 0; o >>= 1) { if (tid < o) sh[tid] += sh[tid + o]; __syncthreads(); }
    if (tid == 0 && hasStats) {
        outStats[0] = loss;
        outStats[1] = expf(-sh[0]);
    }
}

extern "C" void kernel_launch(void* const* d_in, const int* in_sizes, int n_in,
                              void* d_out, int out_size) {
    const float* z   = (const float*)d_in[0];
    const float* emb = (const float*)d_in[1];
    float* out = (float*)d_out;

    int M = in_sizes[0] / DDIM;   // 32768
    int C = in_sizes[1] / DDIM;   // 8192

    static int attr_done = 0;
    if (!attr_done) {
        cudaFuncSetAttribute(hmma_argmin_kernel, cudaFuncAttributeMaxDynamicSharedMemorySize, DYN_SMEM);
        attr_done = 1;
    }

    __half* zh; cudaGetSymbolAddress((void**)&zh, g_zh);
    __half* eh; cudaGetSymbolAddress((void**)&eh, g_eh);

    convert_kernel<<<(M * DDIM / 4 + 255) / 256, 256>>>(z, zh, M * DDIM / 4); // 1
    convert_enorm_kernel<<<C, 128>>>(emb, eh);                        // 2
    hmma_argmin_kernel<<<M / MT, 256, DYN_SMEM>>>(C);                 // 3
    filter_b_kernel<<<NTHREADS_TOT / 256, 256>>>();                   // 4
    exact_kernel<<<1024, 256>>>(z, emb);                              // 5 (fallback fused)
    long long zqN = (long long)M * DDIM;
    int writeCodes = (out_size >= zqN + M) ? 1 : 0;
    gather_kernel<<<M / 2, 256>>>(z, emb, out, out + zqN, writeCodes); // 6
    int hasStats = (out_size >= zqN + M + 2) ? 1 : 0;
    finalize_kernel<<<1, 1024>>>(out + zqN + M, M, C, hasStats);      // 7
}